// round 6
// baseline (speedup 1.0000x reference)
#include <cuda_runtime.h>
#include <cuda_bf16.h>
#include <cstdint>

// Embedding gather + sinusoidal positional encoding.
// out[row, c] = W[ids[row], c] + (row even ? sin : cos)(row * freq(c)),
//   freq(c) = 10000^(-2c/D)
//
// D = 1024, TOKENS = 8192.
// Persistent grid (NBLK CTAs, 4 rows/iteration, stride 4*NBLK):
//  - trig prologue (start/delta/jump rotors, accurate sincosf) ONCE per thread
//  - all 4 row gathers front-batched per iteration (MLP=4)
//  - ids fetched as one int4
//  - streaming stores (__stcs) so the write-once output doesn't evict the
//    gathered W rows from L2 across graph replays.

static constexpr int D       = 1024;
static constexpr int VEC     = 4;
static constexpr int THREADS = D / VEC;   // 256
static constexpr int NBLK    = 592;       // 4 CTAs/SM on 148 SMs
static constexpr int RPI     = 4;         // rows per iteration (multiple of 2)

__global__ __launch_bounds__(THREADS, 5)
void emb_pe_kernel(const int* __restrict__ ids,
                   const float* __restrict__ W,
                   float* __restrict__ out,
                   int rows)
{
    const int t  = threadIdx.x;            // 0..255
    const int c0 = t * VEC;

    // freq(c) = 2^(kexp * c),  kexp = -2*log2(10000)/D
    const float kexp = -13.287712379549449f * 2.0f / (float)D;

    const int row_start = RPI * blockIdx.x;     // multiple of 4 -> even
    const int stride    = RPI * NBLK;           // 2368

    // Rotors (seeded once, accurate):
    //  (s,c)   : angle = row * f       (current even row)
    //  (sd,cd) : +1 row
    //  (sj,cj) : +(stride-3) rows      (jump from row+3 to row+stride)
    float s[VEC], c[VEC], sd[VEC], cd[VEC], sj[VEC], cj[VEC];
#pragma unroll
    for (int i = 0; i < VEC; i++) {
        float freq = exp2f(kexp * (float)(c0 + i));
        sincosf((float)row_start * freq, &s[i], &c[i]);
        sincosf(freq, &sd[i], &cd[i]);
        sincosf((float)(stride - (RPI - 1)) * freq, &sj[i], &cj[i]);
    }

    const float* Wc = W + c0;

    for (int row = row_start; row < rows; row += stride) {
        // One 16B load covers this iteration's 4 ids (uniform across block).
        const int4 ii = *reinterpret_cast<const int4*>(ids + row);

        // Front-batch all 4 gathers (independent LDG.128, MLP=4).
        const float4 v0 = *reinterpret_cast<const float4*>(Wc + (size_t)ii.x * D);
        const float4 v1 = *reinterpret_cast<const float4*>(Wc + (size_t)ii.y * D);
        const float4 v2 = *reinterpret_cast<const float4*>(Wc + (size_t)ii.z * D);
        const float4 v3 = *reinterpret_cast<const float4*>(Wc + (size_t)ii.w * D);

        float* outp = out + (size_t)row * D + c0;

        float4 o;

        // row (even): + sin
        o.x = v0.x + s[0]; o.y = v0.y + s[1]; o.z = v0.z + s[2]; o.w = v0.w + s[3];
        __stcs(reinterpret_cast<float4*>(outp), o);

#pragma unroll
        for (int i = 0; i < VEC; i++) {      // rotate +1
            float ns = fmaf(s[i], cd[i],  c[i] * sd[i]);
            float nc = fmaf(c[i], cd[i], -s[i] * sd[i]);
            s[i] = ns; c[i] = nc;
        }

        // row+1 (odd): + cos
        o.x = v1.x + c[0]; o.y = v1.y + c[1]; o.z = v1.z + c[2]; o.w = v1.w + c[3];
        __stcs(reinterpret_cast<float4*>(outp + D), o);

#pragma unroll
        for (int i = 0; i < VEC; i++) {      // rotate +1
            float ns = fmaf(s[i], cd[i],  c[i] * sd[i]);
            float nc = fmaf(c[i], cd[i], -s[i] * sd[i]);
            s[i] = ns; c[i] = nc;
        }

        // row+2 (even): + sin
        o.x = v2.x + s[0]; o.y = v2.y + s[1]; o.z = v2.z + s[2]; o.w = v2.w + s[3];
        __stcs(reinterpret_cast<float4*>(outp + 2 * D), o);

#pragma unroll
        for (int i = 0; i < VEC; i++) {      // rotate +1
            float ns = fmaf(s[i], cd[i],  c[i] * sd[i]);
            float nc = fmaf(c[i], cd[i], -s[i] * sd[i]);
            s[i] = ns; c[i] = nc;
        }

        // row+3 (odd): + cos
        o.x = v3.x + c[0]; o.y = v3.y + c[1]; o.z = v3.z + c[2]; o.w = v3.w + c[3];
        __stcs(reinterpret_cast<float4*>(outp + 3 * D), o);

#pragma unroll
        for (int i = 0; i < VEC; i++) {      // jump +(stride-3)
            float ns = fmaf(s[i], cj[i],  c[i] * sj[i]);
            float nc = fmaf(c[i], cj[i], -s[i] * sj[i]);
            s[i] = ns; c[i] = nc;
        }
    }
}

extern "C" void kernel_launch(void* const* d_in, const int* in_sizes, int n_in,
                              void* d_out, int out_size)
{
    const int*   ids = (const int*)d_in[0];
    const float* W   = (const float*)d_in[1];
    float*       out = (float*)d_out;

    const int rows = in_sizes[0];             // 8192 tokens
    emb_pe_kernel<<<NBLK, THREADS>>>(ids, W, out, rows);
}

// round 7
// speedup vs baseline: 1.2149x; 1.2149x over previous
#include <cuda_runtime.h>
#include <cuda_bf16.h>
#include <cstdint>

// Embedding gather + sinusoidal positional encoding.
// out[row, c] = W[ids[row], c] + (row even ? sin : cos)(row * freq(c)),
//   freq(c) = 10000^(-2c/D)
//
// D = 1024, TOKENS = 8192. Grid = 2048 CTAs x 4 rows (R4 shape — best so far).
// Prologue trig replaced by Cody-Waite reduction + MUFU __sinf/__cosf
// (~10 instr per sincos vs ~40 for libm sincosf at these argument sizes).

static constexpr int D       = 1024;
static constexpr int VEC     = 4;
static constexpr int THREADS = D / VEC;   // 256
static constexpr int R       = 4;         // rows per block (multiple of 2)

// sincos for 0 <= x <= ~8200: 3-term Cody-Waite reduction mod 2*pi, then MUFU.
// Reduction error ~1e-7 (q <= 1304), MUFU error ~1e-6 on [-pi,pi].
__device__ __forceinline__ void fast_sincos(float x, float& s, float& c)
{
    const float INV2PI = 0.15915494309189535f;
    const float C1 = 6.28125f;            // 2*pi split: C1 exact in 9 bits
    const float C2 = 1.93530717957e-3f;
    const float C3 = 6.1232339957e-10f;
    float q = rintf(x * INV2PI);
    float a = fmaf(-q, C1, x);
    a = fmaf(-q, C2, a);
    a = fmaf(-q, C3, a);
    s = __sinf(a);
    c = __cosf(a);
}

__global__ __launch_bounds__(THREADS, 6)
void emb_pe_kernel(const int* __restrict__ ids,
                   const float* __restrict__ W,
                   float* __restrict__ out)
{
    const int row0 = blockIdx.x * R;          // multiple of 4 -> even
    const int t    = threadIdx.x;             // 0..255
    const int c0   = t * VEC;                 // starting column

    // One 16B load covers this CTA's 4 ids (row0 % 4 == 0 -> aligned).
    const int4 ii = *reinterpret_cast<const int4*>(ids + row0);

    const float* Wc = W + c0;

    // Front-batch all 4 gathers (independent LDG.128, MLP=4).
    const float4 v0 = *reinterpret_cast<const float4*>(Wc + (size_t)ii.x * D);
    const float4 v1 = *reinterpret_cast<const float4*>(Wc + (size_t)ii.y * D);
    const float4 v2 = *reinterpret_cast<const float4*>(Wc + (size_t)ii.z * D);
    const float4 v3 = *reinterpret_cast<const float4*>(Wc + (size_t)ii.w * D);

    // freq(c) = 2^(kexp * c),  kexp = -2*log2(10000)/D  (overlaps load latency)
    const float kexp = -13.287712379549449f * 2.0f / (float)D;
    const float pos0 = (float)row0;

    float s[VEC], c[VEC], sd[VEC], cd[VEC];
#pragma unroll
    for (int i = 0; i < VEC; i++) {
        float freq = exp2f(kexp * (float)(c0 + i));
        fast_sincos(pos0 * freq, s[i], c[i]);   // start rotor
        fast_sincos(freq,        sd[i], cd[i]); // +1 row delta rotor
    }

    float* outp = out + (size_t)row0 * D + c0;
    float4 o;

    // row0 (even): + sin
    o.x = v0.x + s[0]; o.y = v0.y + s[1]; o.z = v0.z + s[2]; o.w = v0.w + s[3];
    *reinterpret_cast<float4*>(outp) = o;

#pragma unroll
    for (int i = 0; i < VEC; i++) {           // rotate +1
        float ns = fmaf(s[i], cd[i],  c[i] * sd[i]);
        float nc = fmaf(c[i], cd[i], -s[i] * sd[i]);
        s[i] = ns; c[i] = nc;
    }

    // row0+1 (odd): + cos
    o.x = v1.x + c[0]; o.y = v1.y + c[1]; o.z = v1.z + c[2]; o.w = v1.w + c[3];
    *reinterpret_cast<float4*>(outp + D) = o;

#pragma unroll
    for (int i = 0; i < VEC; i++) {           // rotate +1
        float ns = fmaf(s[i], cd[i],  c[i] * sd[i]);
        float nc = fmaf(c[i], cd[i], -s[i] * sd[i]);
        s[i] = ns; c[i] = nc;
    }

    // row0+2 (even): + sin
    o.x = v2.x + s[0]; o.y = v2.y + s[1]; o.z = v2.z + s[2]; o.w = v2.w + s[3];
    *reinterpret_cast<float4*>(outp + 2 * D) = o;

#pragma unroll
    for (int i = 0; i < VEC; i++) {           // rotate +1
        float ns = fmaf(s[i], cd[i],  c[i] * sd[i]);
        float nc = fmaf(c[i], cd[i], -s[i] * sd[i]);
        s[i] = ns; c[i] = nc;
    }

    // row0+3 (odd): + cos
    o.x = v3.x + c[0]; o.y = v3.y + c[1]; o.z = v3.z + c[2]; o.w = v3.w + c[3];
    *reinterpret_cast<float4*>(outp + 3 * D) = o;
}

extern "C" void kernel_launch(void* const* d_in, const int* in_sizes, int n_in,
                              void* d_out, int out_size)
{
    const int*   ids = (const int*)d_in[0];
    const float* W   = (const float*)d_in[1];
    float*       out = (float*)d_out;

    const int rows = in_sizes[0];             // 8192 tokens
    emb_pe_kernel<<<rows / R, THREADS>>>(ids, W, out);
}